// round 2
// baseline (speedup 1.0000x reference)
#include <cuda_runtime.h>

#define BHN   128          // B*H
#define SEQ   4096
#define DIM   64
#define SPLIT 8
#define ROWS_PER_SPLIT (SEQ / SPLIT)   // 512
#define CHUNK 32
#define EPSF  1e-6f

typedef unsigned long long u64;

// Scratch (device globals: allocation-free per harness rules)
__device__ float g_ctx_partial[BHN * SPLIT * DIM * DIM]; // 16 MB
__device__ float g_cs_partial [BHN * SPLIT * DIM];
__device__ u64   g_ctxd       [BHN * DIM * DIM];         // 4 MB, DUPLICATED pairs (c,c)

// ---- packed fp32x2 helpers ----
__device__ __forceinline__ void fma2(u64 &d, u64 a, u64 b) {
    asm("fma.rn.f32x2 %0, %1, %2, %0;" : "+l"(d) : "l"(a), "l"(b));
}
__device__ __forceinline__ float2 unpack2(u64 a) {
    float2 f; asm("mov.b64 {%0, %1}, %2;" : "=f"(f.x), "=f"(f.y) : "l"(a)); return f;
}

// ============================================================================
// Kernel 1: partial context = (e^K)^T @ V over an n-split, plus partial colsum.
// 128 threads: tx=tid&7 -> e-tile {4tx..4tx+3} u {32+4tx..}, ty=tid>>3 -> d-tile 4ty..4ty+3.
// e^K stored DUPLICATED in smem => zero MOVs in the inner loop.
// ============================================================================
__global__ __launch_bounds__(128, 6)
void ctx_kernel(const float* __restrict__ kp, const float* __restrict__ vp)
{
    __shared__ __align__(16) u64   s_ekd[CHUNK][DIM]; // 16 KB  (ek,ek) pairs, [n][d]
    __shared__ __align__(16) float s_v  [CHUNK][DIM]; //  8 KB  [n][e]
    __shared__ __align__(16) float s_red[8][DIM];     //  2 KB

    const int tid = threadIdx.x;
    const int tx = tid & 7, ty = tid >> 3;
    const int dcol = tid & 15;                        // staging d-group (const across r)
    const int split = blockIdx.x, bh = blockIdx.y;
    const size_t base = ((size_t)bh * SEQ + (size_t)split * ROWS_PER_SPLIT) * DIM;

    u64 acc[4][4];
#pragma unroll
    for (int i = 0; i < 4; i++)
#pragma unroll
        for (int j = 0; j < 4; j++) acc[i][j] = 0ull;
    float4 cs = make_float4(0.f, 0.f, 0.f, 0.f);      // colsum for d = 4*dcol..+3

    for (int ch = 0; ch < ROWS_PER_SPLIT / CHUNK; ch++) {
        // ---- stage chunk: exp(K) duplicated, V natural ----
#pragma unroll
        for (int r = 0; r < 4; r++) {
            const int idx = r * 128 + tid;            // 0..511 float4s
            const int nl  = idx >> 4;                 // 0..31
            const size_t goff = base + (size_t)(ch * CHUNK + nl) * DIM + 4 * dcol;
            const float4 kk = *(const float4*)(kp + goff);
            const float e0 = __expf(kk.x), e1 = __expf(kk.y),
                        e2 = __expf(kk.z), e3 = __expf(kk.w);
            float4* dst = (float4*)&s_ekd[nl][4 * dcol];
            dst[0] = make_float4(e0, e0, e1, e1);
            dst[1] = make_float4(e2, e2, e3, e3);
            cs.x += e0; cs.y += e1; cs.z += e2; cs.w += e3;
            *(float4*)&s_v[nl][4 * dcol] = *(const float4*)(vp + goff);
        }
        __syncthreads();

        // ---- rank-1 updates: 16 FFMA2 + 4 LDS.128 per n (no MOVs) ----
#pragma unroll 8
        for (int n = 0; n < CHUNK; n++) {
            const ulonglong2 ea = *(const ulonglong2*)&s_ekd[n][4 * ty];     // (d0d0),(d1d1)
            const ulonglong2 eb = *(const ulonglong2*)&s_ekd[n][4 * ty + 2]; // (d2d2),(d3d3)
            const ulonglong2 v0 = *(const ulonglong2*)&s_v[n][4 * tx];       // e 4tx..+3
            const ulonglong2 v1 = *(const ulonglong2*)&s_v[n][32 + 4 * tx];  // e 32+4tx..+3
            fma2(acc[0][0], ea.x, v0.x); fma2(acc[0][1], ea.x, v0.y);
            fma2(acc[0][2], ea.x, v1.x); fma2(acc[0][3], ea.x, v1.y);
            fma2(acc[1][0], ea.y, v0.x); fma2(acc[1][1], ea.y, v0.y);
            fma2(acc[1][2], ea.y, v1.x); fma2(acc[1][3], ea.y, v1.y);
            fma2(acc[2][0], eb.x, v0.x); fma2(acc[2][1], eb.x, v0.y);
            fma2(acc[2][2], eb.x, v1.x); fma2(acc[2][3], eb.x, v1.y);
            fma2(acc[3][0], eb.y, v0.x); fma2(acc[3][1], eb.y, v0.y);
            fma2(acc[3][2], eb.y, v1.x); fma2(acc[3][3], eb.y, v1.y);
        }
        __syncthreads();
    }

    // ---- colsum partial ----
    *(float4*)&s_red[tid >> 4][4 * dcol] = cs;
    __syncthreads();
    const int pbase = bh * SPLIT + split;
    if (tid < DIM) {
        float s = 0.f;
#pragma unroll
        for (int y = 0; y < 8; y++) s += s_red[y][tid];
        g_cs_partial[pbase * DIM + tid] = s;
    }

    // ---- context partial: rows d=4ty+i, cols {4tx, 32+4tx} ----
    float* cp = g_ctx_partial + (size_t)pbase * DIM * DIM;
#pragma unroll
    for (int i = 0; i < 4; i++) {
        const float2 u0 = unpack2(acc[i][0]);
        const float2 u1 = unpack2(acc[i][1]);
        const float2 u2 = unpack2(acc[i][2]);
        const float2 u3 = unpack2(acc[i][3]);
        float* row = cp + (size_t)(4 * ty + i) * DIM;
        *(float4*)(row + 4 * tx)      = make_float4(u0.x, u0.y, u1.x, u1.y);
        *(float4*)(row + 32 + 4 * tx) = make_float4(u2.x, u2.y, u3.x, u3.y);
    }
}

// ============================================================================
// Kernel 2: reduce split partials, normalize, emit DUPLICATED context pairs.
// ============================================================================
__global__ __launch_bounds__(256)
void reduce_kernel()
{
    const int bh = blockIdx.x, tid = threadIdx.x;
    __shared__ float inv[DIM];
    if (tid < DIM) {
        float s = 0.f;
#pragma unroll
        for (int sp = 0; sp < SPLIT; sp++)
            s += g_cs_partial[(bh * SPLIT + sp) * DIM + tid];
        inv[tid] = 1.0f / (s * (1.0f + EPSF));
    }
    __syncthreads();
#pragma unroll
    for (int r = 0; r < 4; r++) {
        const int i4 = r * 256 + tid;            // float4 index over [d][e] (1024)
        float4 s = make_float4(0.f, 0.f, 0.f, 0.f);
#pragma unroll
        for (int sp = 0; sp < SPLIT; sp++) {
            const float4 p = *(const float4*)(g_ctx_partial +
                (size_t)(bh * SPLIT + sp) * DIM * DIM + 4 * i4);
            s.x += p.x; s.y += p.y; s.z += p.z; s.w += p.w;
        }
        const float iv = inv[i4 >> 4];           // d = (4*i4)/64
        s.x *= iv; s.y *= iv; s.z *= iv; s.w *= iv;
        const int d = i4 >> 4, e0 = 4 * (i4 & 15);
        float4* dst = (float4*)(g_ctxd + (size_t)bh * DIM * DIM + d * DIM + e0);
        dst[0] = make_float4(s.x, s.x, s.y, s.y);
        dst[1] = make_float4(s.z, s.z, s.w, s.w);
    }
}

// ============================================================================
// Kernel 3: out = rowsoftmax(Q) @ ctx.  128 threads / 64 rows per block.
// tx=tid&15 -> 4 e-values (XOR chunk-swap for 2-way banks), ty=tid>>4 -> 8 n-rows.
// ============================================================================
__global__ __launch_bounds__(128, 4)
void out_kernel(const float* __restrict__ qp, float* __restrict__ outp)
{
    __shared__ __align__(16) float s_p[DIM][68];   // p^T [d][n], stride 68 (16B-aligned rows)
    __shared__ __align__(16) u64   s_cd[DIM][DIM]; // 32 KB duplicated ctx [d][e]

    const int tid = threadIdx.x;
    const int tx = tid & 15, ty = tid >> 4;
    const int nb = blockIdx.x, bh = blockIdx.y;

    // stage duplicated ctx (plain copy, already dup'd by reduce_kernel)
    {
        const float4* src = (const float4*)(g_ctxd + (size_t)bh * DIM * DIM);
        float4* dst = (float4*)s_cd;
#pragma unroll
        for (int r = 0; r < 16; r++) {
            const int i = r * 128 + tid;
            dst[i] = src[i];
        }
    }

    // row softmax of q: 2 threads per row, 32 elems each
    {
        const int row = tid >> 1, part = tid & 1;
        const float* qr = qp + ((size_t)bh * SEQ + (size_t)nb * 64 + row) * DIM + part * 32;
        float e[32];
#pragma unroll
        for (int i = 0; i < 8; i++) {
            const float4 a = *(const float4*)(qr + 4 * i);
            e[4*i] = a.x; e[4*i+1] = a.y; e[4*i+2] = a.z; e[4*i+3] = a.w;
        }
        float m = e[0];
#pragma unroll
        for (int i = 1; i < 32; i++) m = fmaxf(m, e[i]);
        m = fmaxf(m, __shfl_xor_sync(0xffffffffu, m, 1));
        float s = 0.f;
#pragma unroll
        for (int i = 0; i < 32; i++) { e[i] = __expf(e[i] - m); s += e[i]; }
        s += __shfl_xor_sync(0xffffffffu, s, 1);
        const float rinv = 1.0f / s;
#pragma unroll
        for (int i = 0; i < 32; i++) s_p[part * 32 + i][row] = e[i] * rinv;
    }
    __syncthreads();

    // GEMM: out[n][e] = sum_d p[n][d] * ctx[d][e]
    const int swap = tx >> 3;                       // XOR chunk-swap: max 2-way banks
    const int chunkA = 2 * tx + swap;               // 16B-chunk index (2 u64 each)
    const int chunkB = 2 * tx + 1 - swap;

    u64 acc[4][4];
#pragma unroll
    for (int i = 0; i < 4; i++)
#pragma unroll
        for (int j = 0; j < 4; j++) acc[i][j] = 0ull;

#pragma unroll 8
    for (int d = 0; d < DIM; d++) {
        const ulonglong2 p0 = *(const ulonglong2*)&s_p[d][8 * ty];      // n-pairs
        const ulonglong2 p1 = *(const ulonglong2*)&s_p[d][8 * ty + 4];
        const ulonglong2 cA = *(const ulonglong2*)((const char*)&s_cd[d][0] + chunkA * 16);
        const ulonglong2 cB = *(const ulonglong2*)((const char*)&s_cd[d][0] + chunkB * 16);
        fma2(acc[0][0], p0.x, cA.x); fma2(acc[0][1], p0.x, cA.y);
        fma2(acc[0][2], p0.x, cB.x); fma2(acc[0][3], p0.x, cB.y);
        fma2(acc[1][0], p0.y, cA.x); fma2(acc[1][1], p0.y, cA.y);
        fma2(acc[1][2], p0.y, cB.x); fma2(acc[1][3], p0.y, cB.y);
        fma2(acc[2][0], p1.x, cA.x); fma2(acc[2][1], p1.x, cA.y);
        fma2(acc[2][2], p1.x, cB.x); fma2(acc[2][3], p1.x, cB.y);
        fma2(acc[3][0], p1.y, cA.x); fma2(acc[3][1], p1.y, cA.y);
        fma2(acc[3][2], p1.y, cB.x); fma2(acc[3][3], p1.y, cB.y);
    }

    // undo chunk swap so columns are A-first (e = 4tx..4tx+3)
    if (swap) {
#pragma unroll
        for (int i = 0; i < 4; i++) {
            u64 t0 = acc[i][0], t1 = acc[i][1];
            acc[i][0] = acc[i][2]; acc[i][1] = acc[i][3];
            acc[i][2] = t0;        acc[i][3] = t1;
        }
    }

    // epilogue: acc[i][j] = (out[8ty+2i][e_j], out[8ty+2i+1][e_j]), e_j = 4tx+j
    const size_t obase = ((size_t)bh * SEQ + (size_t)nb * 64) * DIM;
#pragma unroll
    for (int i = 0; i < 4; i++) {
        const float2 u0 = unpack2(acc[i][0]);
        const float2 u1 = unpack2(acc[i][1]);
        const float2 u2 = unpack2(acc[i][2]);
        const float2 u3 = unpack2(acc[i][3]);
        const int r0 = 8 * ty + 2 * i;
        *(float4*)(outp + obase + (size_t)r0 * DIM + 4 * tx) =
            make_float4(u0.x, u1.x, u2.x, u3.x);
        *(float4*)(outp + obase + (size_t)(r0 + 1) * DIM + 4 * tx) =
            make_float4(u0.y, u1.y, u2.y, u3.y);
    }
}

// ============================================================================
extern "C" void kernel_launch(void* const* d_in, const int* in_sizes, int n_in,
                              void* d_out, int out_size)
{
    const float* q = (const float*)d_in[0];
    const float* k = (const float*)d_in[1];
    const float* v = (const float*)d_in[2];
    float* out = (float*)d_out;

    ctx_kernel  <<<dim3(SPLIT, BHN), 128>>>(k, v);
    reduce_kernel<<<BHN, 256>>>();
    out_kernel  <<<dim3(SEQ / 64, BHN), 128>>>(q, out);
}